// round 10
// baseline (speedup 1.0000x reference)
#include <cuda_runtime.h>
#include <cstdint>

// 2x nearest-neighbor upsample — FINAL (exact-grid, guard-free variant).
// in : [16, 64, 256, 256] fp32 = 67108864 floats
// out: [16, 64, 512, 512] fp32
//
// One thread per 32-byte input chunk (8 consecutive input pixels along W):
//   1 x ld.global.v8.f32  +  4 x st.global.v8.f32
// producing a 16-pixel x 2-row output patch. All accesses 256-bit, fully
// coalesced. n8 = 8388608 divides the block size exactly, so the launch is
// exact and the per-thread bounds check is removed.
//
// Roofline status: DRAM-bound at ~6.65 TB/s (~84% of 8 TB/s spec). Seven
// measurements across six structural variants (vector width, MLP, cache
// hints, output-centric, phase-coarsening, block size) all plateau at
// 6.55-6.68 TB/s with SM pipes <10% busy — the HBM controller ceiling for
// a 1:4 R:W streaming mix. Traffic (1.34 GB) is mandatory. At roofline.

static constexpr int W8_IN = 32;   // 8-float chunks per input row (256/8)
static constexpr int W_OUT = 512;  // floats per output row

__global__ __launch_bounds__(256)
void upsample2x_v8_kernel(const float* __restrict__ in,
                          float* __restrict__ out)
{
    int idx = blockIdx.x * blockDim.x + threadIdx.x;

    int row  = idx >> 5;          // idx / 32  (combined b*c*h row index)
    int col8 = idx & (W8_IN - 1); // idx % 32

    const float* ip = in + (size_t)idx * 8;

    float f0, f1, f2, f3, f4, f5, f6, f7;
    asm volatile(
        "ld.global.v8.f32 {%0,%1,%2,%3,%4,%5,%6,%7}, [%8];"
        : "=f"(f0), "=f"(f1), "=f"(f2), "=f"(f3),
          "=f"(f4), "=f"(f5), "=f"(f6), "=f"(f7)
        : "l"(ip));

    float* op = out + (size_t)(row * 2) * W_OUT + (size_t)col8 * 16;

    // Row 0: [f0 f0 f1 f1 f2 f2 f3 f3][f4 f4 f5 f5 f6 f6 f7 f7]
    asm volatile(
        "st.global.v8.f32 [%0], {%1,%2,%3,%4,%5,%6,%7,%8};"
        :: "l"(op),
           "f"(f0), "f"(f0), "f"(f1), "f"(f1),
           "f"(f2), "f"(f2), "f"(f3), "f"(f3) : "memory");
    asm volatile(
        "st.global.v8.f32 [%0], {%1,%2,%3,%4,%5,%6,%7,%8};"
        :: "l"(op + 8),
           "f"(f4), "f"(f4), "f"(f5), "f"(f5),
           "f"(f6), "f"(f6), "f"(f7), "f"(f7) : "memory");
    // Row 1 = duplicate of row 0
    asm volatile(
        "st.global.v8.f32 [%0], {%1,%2,%3,%4,%5,%6,%7,%8};"
        :: "l"(op + W_OUT),
           "f"(f0), "f"(f0), "f"(f1), "f"(f1),
           "f"(f2), "f"(f2), "f"(f3), "f"(f3) : "memory");
    asm volatile(
        "st.global.v8.f32 [%0], {%1,%2,%3,%4,%5,%6,%7,%8};"
        :: "l"(op + W_OUT + 8),
           "f"(f4), "f"(f4), "f"(f5), "f"(f5),
           "f"(f6), "f"(f6), "f"(f7), "f"(f7) : "memory");
}

extern "C" void kernel_launch(void* const* d_in, const int* in_sizes, int n_in,
                              void* d_out, int out_size)
{
    const float* in  = (const float*)d_in[0];
    float*       out = (float*)d_out;

    int n_elems = in_sizes[0];          // 67108864
    int n8      = n_elems / 8;          // 8388608 threads
    int threads = 256;
    int blocks  = n8 / threads;         // 32768, exact

    upsample2x_v8_kernel<<<blocks, threads>>>(in, out);
}